// round 14
// baseline (speedup 1.0000x reference)
#include <cuda_runtime.h>
#include <cuda_fp16.h>
#include <math.h>
#include <stdint.h>

// Problem constants
static constexpr int  BD = 4;
static constexpr int  TD = 4096;
static constexpr int  DM = 1024;           // d_model
static constexpr int  DI = 2048;           // d_inner
static constexpr size_t MROWS = (size_t)BD * TD;   // 16384

// Scratch (fp16 single-plane operands)
__device__ __half g_xn[MROWS * DM];
__device__ __half g_xz[MROWS * 2 * DI];
__device__ __half g_y [MROWS * DI];
__device__ __half g_w1[(size_t)(2 * DI) * DM];
__device__ __half g_w2[(size_t)DM * DI];
__device__ float  g_wbar[DI];

// ===========================================================================
// PTX helpers (sm_80-class — valid at base sm_103 target)
// ===========================================================================
__device__ __forceinline__ uint32_t smem_u32(const void* p) {
    uint32_t a;
    asm("{ .reg .u64 t; cvta.to.shared.u64 t, %1; cvt.u32.u64 %0, t; }"
        : "=r"(a) : "l"(p));
    return a;
}
__device__ __forceinline__ void ldsm_x4(uint32_t* r, uint32_t addr) {
    asm volatile("ldmatrix.sync.aligned.m8n8.x4.shared.b16 {%0,%1,%2,%3}, [%4];"
                 : "=r"(r[0]), "=r"(r[1]), "=r"(r[2]), "=r"(r[3]) : "r"(addr));
}
__device__ __forceinline__ void mma_fp16(float* d, const uint32_t* a,
                                         uint32_t b0, uint32_t b1) {
    asm volatile(
        "mma.sync.aligned.m16n8k16.row.col.f32.f16.f16.f32 "
        "{%0,%1,%2,%3}, {%4,%5,%6,%7}, {%8,%9}, {%0,%1,%2,%3};"
        : "+f"(d[0]), "+f"(d[1]), "+f"(d[2]), "+f"(d[3])
        : "r"(a[0]), "r"(a[1]), "r"(a[2]), "r"(a[3]), "r"(b0), "r"(b1));
}
__device__ __forceinline__ uint32_t pack_h2(float a, float b) {
    __half2 h = __floats2half2_rn(a, b);   // a -> low half
    return *(uint32_t*)&h;
}
// load 8 consecutive halves -> 8 floats
__device__ __forceinline__ void load8h(float* d, const __half* p) {
    uint4 u = *(const uint4*)p;
    float2 f0 = __half22float2(*(__half2*)&u.x);
    float2 f1 = __half22float2(*(__half2*)&u.y);
    float2 f2 = __half22float2(*(__half2*)&u.z);
    float2 f3 = __half22float2(*(__half2*)&u.w);
    d[0]=f0.x; d[1]=f0.y; d[2]=f1.x; d[3]=f1.y;
    d[4]=f2.x; d[5]=f2.y; d[6]=f3.x; d[7]=f3.y;
}
#define CP_ASYNC16(dst, src) \
    asm volatile("cp.async.cg.shared.global [%0], [%1], 16;" \
                 :: "r"(dst), "l"(src) : "memory")
#define CP_COMMIT() asm volatile("cp.async.commit_group;" ::: "memory")
#define CP_WAIT1()  asm volatile("cp.async.wait_group 1;" ::: "memory")
#define CP_WAIT0()  asm volatile("cp.async.wait_group 0;" ::: "memory")

// ===========================================================================
// fp16 HMMA GEMM, templated on BN (256 for GEMM1, 128 for GEMM2 wave-fit).
// BM=128, BK=64; 512 threads (16 warps, 4x4); 3-stage cp.async.
// SMEM rows 144B (128B data + 16B pad) -> conflict-free ldmatrix.
// ===========================================================================
#define G_BM 128
#define G_BK 64
#define ROWB 144
static constexpr int TILE_A = 128 * ROWB;             // 18432 B

template <int BN>
__global__ __launch_bounds__(512, 1)
void gemm_hmma_f16(const __half* __restrict__ Ah,
                   const __half* __restrict__ Wh,
                   const float* __restrict__ bias,
                   const float* __restrict__ resid,   // fp32 or nullptr
                   void* __restrict__ Cout,           // fp16 if out_fp16 else fp32
                   int N, int K, int out_fp16)
{
    constexpr int TILE_BBt = BN * ROWB;
    constexpr int STAGE    = TILE_A + TILE_BBt;
    constexpr int NFRAG    = BN / 64;
    constexpr int WNW      = BN / 4;

    extern __shared__ __align__(16) unsigned char dsm[];
    const uint32_t sb = smem_u32(dsm);

    const int tid  = threadIdx.x;
    const int wid  = tid >> 5, lane = tid & 31;
    const int wm   = wid & 3;
    const int wn   = wid >> 2;
    const int m0   = blockIdx.y * G_BM;
    const int n0   = blockIdx.x * BN;

    const uint32_t frag_off = (uint32_t)((lane & 15) * ROWB + (lane >> 4) * 16);

    float acc[2][NFRAG * 2][4];
    #pragma unroll
    for (int i = 0; i < 2; i++)
        #pragma unroll
        for (int j = 0; j < NFRAG * 2; j++)
            #pragma unroll
            for (int q = 0; q < 4; q++) acc[i][j][q] = 0.f;

    auto issue = [&](int it, int stg) {
        const int k0 = it * G_BK;
        const uint32_t st = sb + stg * STAGE;
        #pragma unroll
        for (int j = 0; j < 2; j++) {            // A: 1024 16B chunks
            int idx = tid + j * 512;
            int row = idx >> 3, c16 = idx & 7;
            CP_ASYNC16(st + (uint32_t)(row * ROWB + c16 * 16),
                       Ah + (size_t)(m0 + row) * K + k0 + c16 * 8);
        }
        #pragma unroll
        for (int j = 0; j < BN / 64; j++) {      // B: BN*8 16B chunks
            int idx = tid + j * 512;
            int row = idx >> 3, c16 = idx & 7;
            CP_ASYNC16(st + TILE_A + (uint32_t)(row * ROWB + c16 * 16),
                       Wh + (size_t)(n0 + row) * K + k0 + c16 * 8);
        }
    };

    const int KC = K / G_BK;
    issue(0, 0); CP_COMMIT();
    issue(1, 1); CP_COMMIT();

    int s_rd = 0, s_wr = 2;
    for (int it = 0; it < KC; it++) {
        if (it + 1 < KC) CP_WAIT1(); else CP_WAIT0();
        __syncthreads();

        if (it + 2 < KC) { issue(it + 2, s_wr); CP_COMMIT(); }

        const uint32_t st = sb + s_rd * STAGE;
        #pragma unroll
        for (int kc = 0; kc < 4; kc++) {
            uint32_t a[2][4], b[NFRAG][4];
            #pragma unroll
            for (int mi = 0; mi < 2; mi++) {
                uint32_t base = (uint32_t)((wm * 32 + mi * 16) * ROWB + kc * 32) + frag_off;
                ldsm_x4(a[mi], st + base);
            }
            #pragma unroll
            for (int nj = 0; nj < NFRAG; nj++) {
                uint32_t base = (uint32_t)((wn * WNW + nj * 16) * ROWB + kc * 32) + frag_off;
                ldsm_x4(b[nj], st + TILE_A + base);
            }
            #pragma unroll
            for (int mi = 0; mi < 2; mi++)
                #pragma unroll
                for (int nj = 0; nj < NFRAG; nj++)
                    #pragma unroll
                    for (int h = 0; h < 2; h++)
                        mma_fp16(acc[mi][nj * 2 + h], a[mi], b[nj][h], b[nj][h + 2]);
        }
        s_rd = (s_rd + 1 == 3) ? 0 : s_rd + 1;
        s_wr = (s_wr + 1 == 3) ? 0 : s_wr + 1;
    }

    // ---- epilogue ----
    const int lg = lane >> 2;
    const int lq = lane & 3;
    if (out_fp16) {
        __half* C = (__half*)Cout;
        #pragma unroll
        for (int mi = 0; mi < 2; mi++) {
            const int mbase = m0 + wm * 32 + mi * 16 + lg;
            #pragma unroll
            for (int ni = 0; ni < NFRAG * 2; ni++) {
                const int n = n0 + wn * WNW + ni * 8 + lq * 2;
                float2 bv = *(const float2*)(bias + n);
                float* a = acc[mi][ni];
                *(uint32_t*)(C + (size_t)mbase * N + n) =
                    pack_h2(a[0] + bv.x, a[1] + bv.y);
                *(uint32_t*)(C + (size_t)(mbase + 8) * N + n) =
                    pack_h2(a[2] + bv.x, a[3] + bv.y);
            }
        }
    } else {
        float* C = (float*)Cout;
        #pragma unroll
        for (int mi = 0; mi < 2; mi++) {
            const int mbase = m0 + wm * 32 + mi * 16 + lg;
            #pragma unroll
            for (int ni = 0; ni < NFRAG * 2; ni++) {
                const int n = n0 + wn * WNW + ni * 8 + lq * 2;
                float2 bv = *(const float2*)(bias + n);
                float* a = acc[mi][ni];
                float2 o0 = make_float2(a[0] + bv.x, a[1] + bv.y);
                float2 o1 = make_float2(a[2] + bv.x, a[3] + bv.y);
                if (resid) {
                    float2 r0 = *(const float2*)(resid + (size_t)mbase * N + n);
                    float2 r1 = *(const float2*)(resid + (size_t)(mbase + 8) * N + n);
                    o0.x += r0.x; o0.y += r0.y;
                    o1.x += r1.x; o1.y += r1.y;
                }
                *(float2*)(C + (size_t)mbase * N + n)       = o0;
                *(float2*)(C + (size_t)(mbase + 8) * N + n) = o1;
            }
        }
    }
}

static constexpr int SMEM_BN256 = 3 * (TILE_A + 256 * ROWB);  // 165888
static constexpr int SMEM_BN128 = 3 * (TILE_A + 128 * ROWB);  // 110592

// ---------------------------------------------------------------------------
// Weight fp32 -> fp16 convert
// ---------------------------------------------------------------------------
__global__ void wconv_k(const float* __restrict__ w,
                        __half* __restrict__ wh, int n4)
{
    int i = blockIdx.x * blockDim.x + threadIdx.x;
    if (i < n4) {
        float4 v = *(const float4*)(w + (size_t)i * 4);
        *(uint2*)(wh + (size_t)i * 4) =
            make_uint2(pack_h2(v.x, v.y), pack_h2(v.z, v.w));
    }
}

// ---------------------------------------------------------------------------
// wbar[c] = (1/16) * sum_s xproj_w[17+s, c]
// ---------------------------------------------------------------------------
__global__ void compute_wbar_k(const float* __restrict__ xproj_w)
{
    int c = blockIdx.x * blockDim.x + threadIdx.x;
    if (c < DI) {
        float s = 0.f;
        #pragma unroll
        for (int k = 0; k < 16; k++)
            s += xproj_w[(size_t)(17 + k) * DI + c];
        g_wbar[c] = s * (1.f / 16.f);
    }
}

// ---------------------------------------------------------------------------
// LayerNorm -> fp16 plane.  Warp-per-row: 8 warps/block, shuffle-only
// reduction, zero block barriers.  grid = MROWS/8.
// ---------------------------------------------------------------------------
__global__ __launch_bounds__(256)
void layernorm_k(const float* __restrict__ x,
                 const float* __restrict__ w,
                 const float* __restrict__ b)
{
    const int tid  = threadIdx.x;
    const int lane = tid & 31, wrp = tid >> 5;
    const size_t row = (size_t)blockIdx.x * 8 + wrp;

    const float4* xr = (const float4*)(x + row * DM);
    float4 v[8];
    float s = 0.f, ss = 0.f;
    #pragma unroll
    for (int j = 0; j < 8; j++) {
        v[j] = xr[lane + j * 32];
        s  += v[j].x + v[j].y + v[j].z + v[j].w;
        ss += v[j].x * v[j].x + v[j].y * v[j].y + v[j].z * v[j].z + v[j].w * v[j].w;
    }
    #pragma unroll
    for (int off = 16; off >= 1; off >>= 1) {
        s  += __shfl_xor_sync(0xffffffffu, s,  off);
        ss += __shfl_xor_sync(0xffffffffu, ss, off);
    }
    const float mu   = s * (1.f / DM);
    const float var  = ss * (1.f / DM) - mu * mu;
    const float rstd = rsqrtf(var + 1e-5f);

    #pragma unroll
    for (int j = 0; j < 8; j++) {
        const int c = (lane + j * 32) * 4;
        const float4 wv = *(const float4*)(w + c);
        const float4 bv = *(const float4*)(b + c);
        float o0 = (v[j].x - mu) * rstd * wv.x + bv.x;
        float o1 = (v[j].y - mu) * rstd * wv.y + bv.y;
        float o2 = (v[j].z - mu) * rstd * wv.z + bv.z;
        float o3 = (v[j].w - mu) * rstd * wv.w + bv.w;
        *(uint2*)(g_xn + row * DM + c) =
            make_uint2(pack_h2(o0, o1), pack_h2(o2, o3));
    }
}

// ---------------------------------------------------------------------------
// Fused mid: conv(4) + SiLU + gate + z-gate -> fp16 plane of y.
// TWO timesteps per __syncthreads (independent gates), parity-buffered
// reduction scratch.  Per-t arithmetic order identical to previous rounds.
// ---------------------------------------------------------------------------
#define TT 16

__global__ __launch_bounds__(256)
void fused_mid_k(const float* __restrict__ conv_w,
                 const float* __restrict__ conv_b,
                 const float* __restrict__ Dp)
{
    __shared__ float2 red[2][8];
    const int b   = blockIdx.y;
    const int t0  = blockIdx.x * TT;
    const int tid = threadIdx.x;
    const int lane = tid & 31, wrp = tid >> 5;
    const int c0 = tid * 8;

    float cw0[8], cw1[8], cw2[8], cw3[8], cb[8], wb[8], dd[8];
    #pragma unroll
    for (int i = 0; i < 8; i++) {
        float4 q = *(const float4*)(conv_w + (size_t)(c0 + i) * 4);
        cw0[i] = q.x; cw1[i] = q.y; cw2[i] = q.z; cw3[i] = q.w;
        cb[i] = conv_b[c0 + i];
        wb[i] = g_wbar[c0 + i];
        dd[i] = Dp[c0 + i];
    }

    float w0[8], w1[8], w2[8];
    #pragma unroll
    for (int j = 0; j < 3; j++) {
        int t = t0 - 3 + j;
        float* dst = (j == 0) ? w0 : (j == 1) ? w1 : w2;
        if (t >= 0) {
            load8h(dst, g_xz + ((size_t)b * TD + t) * (2 * DI) + c0);
        } else {
            #pragma unroll
            for (int i = 0; i < 8; i++) dst[i] = 0.f;
        }
    }

    for (int tt = 0; tt < TT; tt += 2) {
        const int t = t0 + tt;
        const int par = (tt >> 1) & 1;
        const size_t rb0 = ((size_t)b * TD + t) * (2 * DI);
        const size_t rb1 = rb0 + 2 * DI;

        float cur0[8], cur1[8];
        load8h(cur0, g_xz + rb0 + c0);
        load8h(cur1, g_xz + rb1 + c0);

        float xc0[8], xc1[8];
        float p0 = 0.f, p1 = 0.f;
        #pragma unroll
        for (int i = 0; i < 8; i++) {
            float a0 = cb[i] + w0[i]*cw0[i] + w1[i]*cw1[i] + w2[i]*cw2[i] + cur0[i]*cw3[i];
            float a1 = cb[i] + w1[i]*cw0[i] + w2[i]*cw1[i] + cur0[i]*cw2[i] + cur1[i]*cw3[i];
            float s0 = 1.f / (1.f + __expf(-a0));
            float s1 = 1.f / (1.f + __expf(-a1));
            xc0[i] = a0 * s0;
            xc1[i] = a1 * s1;
            p0 += xc0[i] * wb[i];
            p1 += xc1[i] * wb[i];
        }

        #pragma unroll
        for (int off = 16; off >= 1; off >>= 1) {
            p0 += __shfl_xor_sync(0xffffffffu, p0, off);
            p1 += __shfl_xor_sync(0xffffffffu, p1, off);
        }
        if (lane == 0) red[par][wrp] = make_float2(p0, p1);
        __syncthreads();
        float g0 = 0.f, g1 = 0.f;
        #pragma unroll
        for (int k = 0; k < 8; k++) { g0 += red[par][k].x; g1 += red[par][k].y; }
        const float gate0 = 1.f / (1.f + __expf(-g0));
        const float gate1 = 1.f / (1.f + __expf(-g1));

        float zv0[8], zv1[8];
        load8h(zv0, g_xz + rb0 + DI + c0);
        load8h(zv1, g_xz + rb1 + DI + c0);

        float out0[8], out1[8];
        #pragma unroll
        for (int i = 0; i < 8; i++) {
            float sz0 = zv0[i] / (1.f + __expf(-zv0[i]));
            float sz1 = zv1[i] / (1.f + __expf(-zv1[i]));
            out0[i] = xc0[i] * (gate0 + dd[i]) * sz0;
            out1[i] = xc1[i] * (gate1 + dd[i]) * sz1;
        }

        size_t yo = ((size_t)b * TD + t) * DI + c0;
        *(uint4*)(g_y + yo) = make_uint4(
            pack_h2(out0[0], out0[1]), pack_h2(out0[2], out0[3]),
            pack_h2(out0[4], out0[5]), pack_h2(out0[6], out0[7]));
        *(uint4*)(g_y + yo + DI) = make_uint4(
            pack_h2(out1[0], out1[1]), pack_h2(out1[2], out1[3]),
            pack_h2(out1[4], out1[5]), pack_h2(out1[6], out1[7]));

        #pragma unroll
        for (int i = 0; i < 8; i++) { w0[i] = w2[i]; w1[i] = cur0[i]; w2[i] = cur1[i]; }
    }
}

// ---------------------------------------------------------------------------
extern "C" void kernel_launch(void* const* d_in, const int* in_sizes, int n_in,
                              void* d_out, int out_size)
{
    const float* x       = (const float*)d_in[0];
    const float* norm_w  = (const float*)d_in[1];
    const float* norm_b  = (const float*)d_in[2];
    const float* in_w    = (const float*)d_in[3];
    const float* in_b    = (const float*)d_in[4];
    const float* conv_w  = (const float*)d_in[5];
    const float* conv_b  = (const float*)d_in[6];
    const float* xproj_w = (const float*)d_in[7];
    const float* Dp      = (const float*)d_in[9];
    const float* out_w   = (const float*)d_in[10];
    const float* out_b   = (const float*)d_in[11];
    float* out = (float*)d_out;

    __half *xn_p, *xz_p, *y_p, *w1_p, *w2_p;
    cudaGetSymbolAddress((void**)&xn_p, g_xn);
    cudaGetSymbolAddress((void**)&xz_p, g_xz);
    cudaGetSymbolAddress((void**)&y_p,  g_y);
    cudaGetSymbolAddress((void**)&w1_p, g_w1);
    cudaGetSymbolAddress((void**)&w2_p, g_w2);

    static int smem_set = 0;
    if (!smem_set) {
        cudaFuncSetAttribute(gemm_hmma_f16<256>,
                             cudaFuncAttributeMaxDynamicSharedMemorySize, SMEM_BN256);
        cudaFuncSetAttribute(gemm_hmma_f16<128>,
                             cudaFuncAttributeMaxDynamicSharedMemorySize, SMEM_BN128);
        smem_set = 1;
    }

    // weight converts (elementwise, tiny)
    {
        int n4a = (2 * DI) * DM / 4;
        wconv_k<<<(n4a + 255) / 256, 256>>>(in_w, w1_p, n4a);
        int n4b = DM * DI / 4;
        wconv_k<<<(n4b + 255) / 256, 256>>>(out_w, w2_p, n4b);
    }
    compute_wbar_k<<<(DI + 255) / 256, 256>>>(xproj_w);
    layernorm_k<<<(int)(MROWS / 8), 256>>>(x, norm_w, norm_b);

    // GEMM1: xz = xn @ in_w.T + in_b   (M=16384, N=4096, K=1024) -> fp16
    gemm_hmma_f16<256><<<dim3((2 * DI) / 256, (int)MROWS / G_BM), 512, SMEM_BN256>>>(
        xn_p, w1_p, in_b, nullptr, xz_p, 2 * DI, DM, 1);

    // conv + silu + gate + z-gate -> y (fp16)
    fused_mid_k<<<dim3(TD / TT, BD), 256>>>(conv_w, conv_b, Dp);

    // GEMM2: out = y @ out_w.T + out_b + x  (M=16384, N=1024, K=2048) -> fp32
    gemm_hmma_f16<128><<<dim3(DM / 128, (int)MROWS / G_BM), 512, SMEM_BN128>>>(
        y_p, w2_p, out_b, x, out, DM, DI, 0);
}

// round 15
// speedup vs baseline: 1.0531x; 1.0531x over previous
#include <cuda_runtime.h>
#include <cuda_fp16.h>
#include <math.h>
#include <stdint.h>

// Problem constants
static constexpr int  BD = 4;
static constexpr int  TD = 4096;
static constexpr int  DM = 1024;           // d_model
static constexpr int  DI = 2048;           // d_inner
static constexpr size_t MROWS = (size_t)BD * TD;   // 16384

// Scratch (fp16 single-plane operands)
__device__ __half g_xn[MROWS * DM];
__device__ __half g_xz[MROWS * 2 * DI];
__device__ __half g_y [MROWS * DI];
__device__ __half g_w1[(size_t)(2 * DI) * DM];
__device__ __half g_w2[(size_t)DM * DI];
__device__ float  g_wbar[DI];

// ===========================================================================
// PTX helpers (sm_80-class — valid at base sm_103 target)
// ===========================================================================
__device__ __forceinline__ uint32_t smem_u32(const void* p) {
    uint32_t a;
    asm("{ .reg .u64 t; cvta.to.shared.u64 t, %1; cvt.u32.u64 %0, t; }"
        : "=r"(a) : "l"(p));
    return a;
}
__device__ __forceinline__ void ldsm_x4(uint32_t* r, uint32_t addr) {
    asm volatile("ldmatrix.sync.aligned.m8n8.x4.shared.b16 {%0,%1,%2,%3}, [%4];"
                 : "=r"(r[0]), "=r"(r[1]), "=r"(r[2]), "=r"(r[3]) : "r"(addr));
}
__device__ __forceinline__ void mma_fp16(float* d, const uint32_t* a,
                                         uint32_t b0, uint32_t b1) {
    asm volatile(
        "mma.sync.aligned.m16n8k16.row.col.f32.f16.f16.f32 "
        "{%0,%1,%2,%3}, {%4,%5,%6,%7}, {%8,%9}, {%0,%1,%2,%3};"
        : "+f"(d[0]), "+f"(d[1]), "+f"(d[2]), "+f"(d[3])
        : "r"(a[0]), "r"(a[1]), "r"(a[2]), "r"(a[3]), "r"(b0), "r"(b1));
}
__device__ __forceinline__ uint32_t pack_h2(float a, float b) {
    __half2 h = __floats2half2_rn(a, b);   // a -> low half
    return *(uint32_t*)&h;
}
// load 8 consecutive halves -> 8 floats
__device__ __forceinline__ void load8h(float* d, const __half* p) {
    uint4 u = *(const uint4*)p;
    float2 f0 = __half22float2(*(__half2*)&u.x);
    float2 f1 = __half22float2(*(__half2*)&u.y);
    float2 f2 = __half22float2(*(__half2*)&u.z);
    float2 f3 = __half22float2(*(__half2*)&u.w);
    d[0]=f0.x; d[1]=f0.y; d[2]=f1.x; d[3]=f1.y;
    d[4]=f2.x; d[5]=f2.y; d[6]=f3.x; d[7]=f3.y;
}
#define CP_ASYNC16(dst, src) \
    asm volatile("cp.async.cg.shared.global [%0], [%1], 16;" \
                 :: "r"(dst), "l"(src) : "memory")
#define CP_COMMIT() asm volatile("cp.async.commit_group;" ::: "memory")
#define CP_WAIT1()  asm volatile("cp.async.wait_group 1;" ::: "memory")
#define CP_WAIT0()  asm volatile("cp.async.wait_group 0;" ::: "memory")

// ===========================================================================
// fp16 HMMA GEMM, templated on BN (256 for GEMM1, 128 for GEMM2 wave-fit).
// BM=128, BK=64; 512 threads (16 warps, 4x4); 3-stage cp.async.
// SMEM rows 144B (128B data + 16B pad) -> conflict-free ldmatrix.
// ===========================================================================
#define G_BM 128
#define G_BK 64
#define ROWB 144
static constexpr int TILE_A = 128 * ROWB;             // 18432 B

template <int BN>
__global__ __launch_bounds__(512, 1)
void gemm_hmma_f16(const __half* __restrict__ Ah,
                   const __half* __restrict__ Wh,
                   const float* __restrict__ bias,
                   const float* __restrict__ resid,   // fp32 or nullptr
                   void* __restrict__ Cout,           // fp16 if out_fp16 else fp32
                   int N, int K, int out_fp16)
{
    constexpr int TILE_BBt = BN * ROWB;
    constexpr int STAGE    = TILE_A + TILE_BBt;
    constexpr int NFRAG    = BN / 64;
    constexpr int WNW      = BN / 4;

    extern __shared__ __align__(16) unsigned char dsm[];
    const uint32_t sb = smem_u32(dsm);

    const int tid  = threadIdx.x;
    const int wid  = tid >> 5, lane = tid & 31;
    const int wm   = wid & 3;
    const int wn   = wid >> 2;
    const int m0   = blockIdx.y * G_BM;
    const int n0   = blockIdx.x * BN;

    const uint32_t frag_off = (uint32_t)((lane & 15) * ROWB + (lane >> 4) * 16);

    float acc[2][NFRAG * 2][4];
    #pragma unroll
    for (int i = 0; i < 2; i++)
        #pragma unroll
        for (int j = 0; j < NFRAG * 2; j++)
            #pragma unroll
            for (int q = 0; q < 4; q++) acc[i][j][q] = 0.f;

    auto issue = [&](int it, int stg) {
        const int k0 = it * G_BK;
        const uint32_t st = sb + stg * STAGE;
        #pragma unroll
        for (int j = 0; j < 2; j++) {            // A: 1024 16B chunks
            int idx = tid + j * 512;
            int row = idx >> 3, c16 = idx & 7;
            CP_ASYNC16(st + (uint32_t)(row * ROWB + c16 * 16),
                       Ah + (size_t)(m0 + row) * K + k0 + c16 * 8);
        }
        #pragma unroll
        for (int j = 0; j < BN / 64; j++) {      // B: BN*8 16B chunks
            int idx = tid + j * 512;
            int row = idx >> 3, c16 = idx & 7;
            CP_ASYNC16(st + TILE_A + (uint32_t)(row * ROWB + c16 * 16),
                       Wh + (size_t)(n0 + row) * K + k0 + c16 * 8);
        }
    };

    const int KC = K / G_BK;
    issue(0, 0); CP_COMMIT();
    issue(1, 1); CP_COMMIT();

    int s_rd = 0, s_wr = 2;
    for (int it = 0; it < KC; it++) {
        if (it + 1 < KC) CP_WAIT1(); else CP_WAIT0();
        __syncthreads();

        if (it + 2 < KC) { issue(it + 2, s_wr); CP_COMMIT(); }

        const uint32_t st = sb + s_rd * STAGE;
        #pragma unroll
        for (int kc = 0; kc < 4; kc++) {
            uint32_t a[2][4], b[NFRAG][4];
            #pragma unroll
            for (int mi = 0; mi < 2; mi++) {
                uint32_t base = (uint32_t)((wm * 32 + mi * 16) * ROWB + kc * 32) + frag_off;
                ldsm_x4(a[mi], st + base);
            }
            #pragma unroll
            for (int nj = 0; nj < NFRAG; nj++) {
                uint32_t base = (uint32_t)((wn * WNW + nj * 16) * ROWB + kc * 32) + frag_off;
                ldsm_x4(b[nj], st + TILE_A + base);
            }
            #pragma unroll
            for (int mi = 0; mi < 2; mi++)
                #pragma unroll
                for (int nj = 0; nj < NFRAG; nj++)
                    #pragma unroll
                    for (int h = 0; h < 2; h++)
                        mma_fp16(acc[mi][nj * 2 + h], a[mi], b[nj][h], b[nj][h + 2]);
        }
        s_rd = (s_rd + 1 == 3) ? 0 : s_rd + 1;
        s_wr = (s_wr + 1 == 3) ? 0 : s_wr + 1;
    }

    // ---- epilogue ----
    const int lg = lane >> 2;
    const int lq = lane & 3;
    if (out_fp16) {
        __half* C = (__half*)Cout;
        #pragma unroll
        for (int mi = 0; mi < 2; mi++) {
            const int mbase = m0 + wm * 32 + mi * 16 + lg;
            #pragma unroll
            for (int ni = 0; ni < NFRAG * 2; ni++) {
                const int n = n0 + wn * WNW + ni * 8 + lq * 2;
                float2 bv = *(const float2*)(bias + n);
                float* a = acc[mi][ni];
                *(uint32_t*)(C + (size_t)mbase * N + n) =
                    pack_h2(a[0] + bv.x, a[1] + bv.y);
                *(uint32_t*)(C + (size_t)(mbase + 8) * N + n) =
                    pack_h2(a[2] + bv.x, a[3] + bv.y);
            }
        }
    } else {
        float* C = (float*)Cout;
        #pragma unroll
        for (int mi = 0; mi < 2; mi++) {
            const int mbase = m0 + wm * 32 + mi * 16 + lg;
            #pragma unroll
            for (int ni = 0; ni < NFRAG * 2; ni++) {
                const int n = n0 + wn * WNW + ni * 8 + lq * 2;
                float2 bv = *(const float2*)(bias + n);
                float* a = acc[mi][ni];
                float2 o0 = make_float2(a[0] + bv.x, a[1] + bv.y);
                float2 o1 = make_float2(a[2] + bv.x, a[3] + bv.y);
                if (resid) {
                    float2 r0 = *(const float2*)(resid + (size_t)mbase * N + n);
                    float2 r1 = *(const float2*)(resid + (size_t)(mbase + 8) * N + n);
                    o0.x += r0.x; o0.y += r0.y;
                    o1.x += r1.x; o1.y += r1.y;
                }
                *(float2*)(C + (size_t)mbase * N + n)       = o0;
                *(float2*)(C + (size_t)(mbase + 8) * N + n) = o1;
            }
        }
    }
}

static constexpr int SMEM_BN256 = 3 * (TILE_A + 256 * ROWB);  // 165888
static constexpr int SMEM_BN128 = 3 * (TILE_A + 128 * ROWB);  // 110592

// ---------------------------------------------------------------------------
// Weight fp32 -> fp16 convert
// ---------------------------------------------------------------------------
__global__ void wconv_k(const float* __restrict__ w,
                        __half* __restrict__ wh, int n4)
{
    int i = blockIdx.x * blockDim.x + threadIdx.x;
    if (i < n4) {
        float4 v = *(const float4*)(w + (size_t)i * 4);
        *(uint2*)(wh + (size_t)i * 4) =
            make_uint2(pack_h2(v.x, v.y), pack_h2(v.z, v.w));
    }
}

// ---------------------------------------------------------------------------
// wbar[c] = (1/16) * sum_s xproj_w[17+s, c]
// ---------------------------------------------------------------------------
__global__ void compute_wbar_k(const float* __restrict__ xproj_w)
{
    int c = blockIdx.x * blockDim.x + threadIdx.x;
    if (c < DI) {
        float s = 0.f;
        #pragma unroll
        for (int k = 0; k < 16; k++)
            s += xproj_w[(size_t)(17 + k) * DI + c];
        g_wbar[c] = s * (1.f / 16.f);
    }
}

// ---------------------------------------------------------------------------
// LayerNorm -> fp16 plane.  Warp-per-row: 8 warps/block, shuffle-only
// reduction, zero block barriers.  grid = MROWS/8.  (Measured 16.8us.)
// ---------------------------------------------------------------------------
__global__ __launch_bounds__(256)
void layernorm_k(const float* __restrict__ x,
                 const float* __restrict__ w,
                 const float* __restrict__ b)
{
    const int tid  = threadIdx.x;
    const int lane = tid & 31, wrp = tid >> 5;
    const size_t row = (size_t)blockIdx.x * 8 + wrp;

    const float4* xr = (const float4*)(x + row * DM);
    float4 v[8];
    float s = 0.f, ss = 0.f;
    #pragma unroll
    for (int j = 0; j < 8; j++) {
        v[j] = xr[lane + j * 32];
        s  += v[j].x + v[j].y + v[j].z + v[j].w;
        ss += v[j].x * v[j].x + v[j].y * v[j].y + v[j].z * v[j].z + v[j].w * v[j].w;
    }
    #pragma unroll
    for (int off = 16; off >= 1; off >>= 1) {
        s  += __shfl_xor_sync(0xffffffffu, s,  off);
        ss += __shfl_xor_sync(0xffffffffu, ss, off);
    }
    const float mu   = s * (1.f / DM);
    const float var  = ss * (1.f / DM) - mu * mu;
    const float rstd = rsqrtf(var + 1e-5f);

    #pragma unroll
    for (int j = 0; j < 8; j++) {
        const int c = (lane + j * 32) * 4;
        const float4 wv = *(const float4*)(w + c);
        const float4 bv = *(const float4*)(b + c);
        float o0 = (v[j].x - mu) * rstd * wv.x + bv.x;
        float o1 = (v[j].y - mu) * rstd * wv.y + bv.y;
        float o2 = (v[j].z - mu) * rstd * wv.z + bv.z;
        float o3 = (v[j].w - mu) * rstd * wv.w + bv.w;
        *(uint2*)(g_xn + row * DM + c) =
            make_uint2(pack_h2(o0, o1), pack_h2(o2, o3));
    }
}

// ---------------------------------------------------------------------------
// Fused mid: conv(4) + SiLU + gate + z-gate -> fp16 plane of y.
// R13 single-timestep form (one barrier per t, parity scratch, no spills).
// R14's 2-timestep pairing REGRESSED (+50us) via register spills — reverted.
// ---------------------------------------------------------------------------
#define TT 16

__global__ __launch_bounds__(256)
void fused_mid_k(const float* __restrict__ conv_w,
                 const float* __restrict__ conv_b,
                 const float* __restrict__ Dp)
{
    __shared__ float red[2][8];
    const int b   = blockIdx.y;
    const int t0  = blockIdx.x * TT;
    const int tid = threadIdx.x;
    const int lane = tid & 31, wrp = tid >> 5;
    const int c0 = tid * 8;

    float cw0[8], cw1[8], cw2[8], cw3[8], cb[8], wb[8], dd[8];
    #pragma unroll
    for (int i = 0; i < 8; i++) {
        float4 q = *(const float4*)(conv_w + (size_t)(c0 + i) * 4);
        cw0[i] = q.x; cw1[i] = q.y; cw2[i] = q.z; cw3[i] = q.w;
        cb[i] = conv_b[c0 + i];
        wb[i] = g_wbar[c0 + i];
        dd[i] = Dp[c0 + i];
    }

    float w0[8], w1[8], w2[8];
    #pragma unroll
    for (int j = 0; j < 3; j++) {
        int t = t0 - 3 + j;
        float* dst = (j == 0) ? w0 : (j == 1) ? w1 : w2;
        if (t >= 0) {
            load8h(dst, g_xz + ((size_t)b * TD + t) * (2 * DI) + c0);
        } else {
            #pragma unroll
            for (int i = 0; i < 8; i++) dst[i] = 0.f;
        }
    }

    for (int tt = 0; tt < TT; tt++) {
        const int t = t0 + tt;
        const int par = tt & 1;
        const size_t rb = ((size_t)b * TD + t) * (2 * DI);

        float cur[8];
        load8h(cur, g_xz + rb + c0);

        float xc[8], partial = 0.f;
        #pragma unroll
        for (int i = 0; i < 8; i++) {
            float a = cb[i] + w0[i]*cw0[i] + w1[i]*cw1[i] + w2[i]*cw2[i] + cur[i]*cw3[i];
            float sg = 1.f / (1.f + __expf(-a));
            xc[i] = a * sg;
            partial += xc[i] * wb[i];
        }

        #pragma unroll
        for (int off = 16; off >= 1; off >>= 1)
            partial += __shfl_xor_sync(0xffffffffu, partial, off);
        if (lane == 0) red[par][wrp] = partial;
        __syncthreads();
        float ssum = 0.f;
        #pragma unroll
        for (int k = 0; k < 8; k++) ssum += red[par][k];
        const float gate = 1.f / (1.f + __expf(-ssum));

        float zv[8];
        load8h(zv, g_xz + rb + DI + c0);

        float out[8];
        #pragma unroll
        for (int i = 0; i < 8; i++) {
            float sz = zv[i] / (1.f + __expf(-zv[i]));
            out[i] = xc[i] * (gate + dd[i]) * sz;
        }

        size_t yo = ((size_t)b * TD + t) * DI + c0;
        *(uint4*)(g_y + yo) = make_uint4(
            pack_h2(out[0], out[1]), pack_h2(out[2], out[3]),
            pack_h2(out[4], out[5]), pack_h2(out[6], out[7]));

        #pragma unroll
        for (int i = 0; i < 8; i++) { w0[i] = w1[i]; w1[i] = w2[i]; w2[i] = cur[i]; }
    }
}

// ---------------------------------------------------------------------------
extern "C" void kernel_launch(void* const* d_in, const int* in_sizes, int n_in,
                              void* d_out, int out_size)
{
    const float* x       = (const float*)d_in[0];
    const float* norm_w  = (const float*)d_in[1];
    const float* norm_b  = (const float*)d_in[2];
    const float* in_w    = (const float*)d_in[3];
    const float* in_b    = (const float*)d_in[4];
    const float* conv_w  = (const float*)d_in[5];
    const float* conv_b  = (const float*)d_in[6];
    const float* xproj_w = (const float*)d_in[7];
    const float* Dp      = (const float*)d_in[9];
    const float* out_w   = (const float*)d_in[10];
    const float* out_b   = (const float*)d_in[11];
    float* out = (float*)d_out;

    __half *xn_p, *xz_p, *y_p, *w1_p, *w2_p;
    cudaGetSymbolAddress((void**)&xn_p, g_xn);
    cudaGetSymbolAddress((void**)&xz_p, g_xz);
    cudaGetSymbolAddress((void**)&y_p,  g_y);
    cudaGetSymbolAddress((void**)&w1_p, g_w1);
    cudaGetSymbolAddress((void**)&w2_p, g_w2);

    static int smem_set = 0;
    if (!smem_set) {
        cudaFuncSetAttribute(gemm_hmma_f16<256>,
                             cudaFuncAttributeMaxDynamicSharedMemorySize, SMEM_BN256);
        cudaFuncSetAttribute(gemm_hmma_f16<128>,
                             cudaFuncAttributeMaxDynamicSharedMemorySize, SMEM_BN128);
        smem_set = 1;
    }

    // weight converts (elementwise, tiny)
    {
        int n4a = (2 * DI) * DM / 4;
        wconv_k<<<(n4a + 255) / 256, 256>>>(in_w, w1_p, n4a);
        int n4b = DM * DI / 4;
        wconv_k<<<(n4b + 255) / 256, 256>>>(out_w, w2_p, n4b);
    }
    compute_wbar_k<<<(DI + 255) / 256, 256>>>(xproj_w);
    layernorm_k<<<(int)(MROWS / 8), 256>>>(x, norm_w, norm_b);

    // GEMM1: xz = xn @ in_w.T + in_b   (M=16384, N=4096, K=1024) -> fp16
    gemm_hmma_f16<256><<<dim3((2 * DI) / 256, (int)MROWS / G_BM), 512, SMEM_BN256>>>(
        xn_p, w1_p, in_b, nullptr, xz_p, 2 * DI, DM, 1);

    // conv + silu + gate + z-gate -> y (fp16)
    fused_mid_k<<<dim3(TD / TT, BD), 256>>>(conv_w, conv_b, Dp);

    // GEMM2: out = y @ out_w.T + out_b + x  (M=16384, N=1024, K=2048) -> fp32
    gemm_hmma_f16<128><<<dim3(DM / 128, (int)MROWS / G_BM), 512, SMEM_BN128>>>(
        y_p, w2_p, out_b, x, out, DM, DI, 0);
}

// round 16
// speedup vs baseline: 1.0653x; 1.0115x over previous
#include <cuda_runtime.h>
#include <cuda_fp16.h>
#include <math.h>
#include <stdint.h>

// Problem constants
static constexpr int  BD = 4;
static constexpr int  TD = 4096;
static constexpr int  DM = 1024;           // d_model
static constexpr int  DI = 2048;           // d_inner
static constexpr size_t MROWS = (size_t)BD * TD;   // 16384

// Scratch (fp16 single-plane operands)
__device__ __half g_xn[MROWS * DM];
__device__ __half g_xz[MROWS * 2 * DI];
__device__ __half g_y [MROWS * DI];
__device__ __half g_w1[(size_t)(2 * DI) * DM];
__device__ __half g_w2[(size_t)DM * DI];
__device__ float  g_wbar[DI];

// ===========================================================================
// PTX helpers (sm_80-class — valid at base sm_103 target)
// ===========================================================================
__device__ __forceinline__ uint32_t smem_u32(const void* p) {
    uint32_t a;
    asm("{ .reg .u64 t; cvta.to.shared.u64 t, %1; cvt.u32.u64 %0, t; }"
        : "=r"(a) : "l"(p));
    return a;
}
__device__ __forceinline__ void ldsm_x4(uint32_t* r, uint32_t addr) {
    asm volatile("ldmatrix.sync.aligned.m8n8.x4.shared.b16 {%0,%1,%2,%3}, [%4];"
                 : "=r"(r[0]), "=r"(r[1]), "=r"(r[2]), "=r"(r[3]) : "r"(addr));
}
__device__ __forceinline__ void mma_fp16(float* d, const uint32_t* a,
                                         uint32_t b0, uint32_t b1) {
    asm volatile(
        "mma.sync.aligned.m16n8k16.row.col.f32.f16.f16.f32 "
        "{%0,%1,%2,%3}, {%4,%5,%6,%7}, {%8,%9}, {%0,%1,%2,%3};"
        : "+f"(d[0]), "+f"(d[1]), "+f"(d[2]), "+f"(d[3])
        : "r"(a[0]), "r"(a[1]), "r"(a[2]), "r"(a[3]), "r"(b0), "r"(b1));
}
__device__ __forceinline__ uint32_t pack_h2(float a, float b) {
    __half2 h = __floats2half2_rn(a, b);   // a -> low half
    return *(uint32_t*)&h;
}
// load 8 consecutive halves -> 8 floats
__device__ __forceinline__ void load8h(float* d, const __half* p) {
    uint4 u = *(const uint4*)p;
    float2 f0 = __half22float2(*(__half2*)&u.x);
    float2 f1 = __half22float2(*(__half2*)&u.y);
    float2 f2 = __half22float2(*(__half2*)&u.z);
    float2 f3 = __half22float2(*(__half2*)&u.w);
    d[0]=f0.x; d[1]=f0.y; d[2]=f1.x; d[3]=f1.y;
    d[4]=f2.x; d[5]=f2.y; d[6]=f3.x; d[7]=f3.y;
}
#define CP_ASYNC16(dst, src) \
    asm volatile("cp.async.cg.shared.global [%0], [%1], 16;" \
                 :: "r"(dst), "l"(src) : "memory")
#define CP_COMMIT() asm volatile("cp.async.commit_group;" ::: "memory")
#define CP_WAIT1()  asm volatile("cp.async.wait_group 1;" ::: "memory")
#define CP_WAIT0()  asm volatile("cp.async.wait_group 0;" ::: "memory")

// ===========================================================================
// fp16 HMMA GEMM, templated on BN (256 for GEMM1, 128 for GEMM2 wave-fit).
// BM=128, BK=64; 512 threads (16 warps, 4x4); 3-stage cp.async.
// SMEM rows 144B (128B data + 16B pad) -> conflict-free ldmatrix.
// ===========================================================================
#define G_BM 128
#define G_BK 64
#define ROWB 144
static constexpr int TILE_A = 128 * ROWB;             // 18432 B

template <int BN>
__global__ __launch_bounds__(512, 1)
void gemm_hmma_f16(const __half* __restrict__ Ah,
                   const __half* __restrict__ Wh,
                   const float* __restrict__ bias,
                   const float* __restrict__ resid,   // fp32 or nullptr
                   void* __restrict__ Cout,           // fp16 if out_fp16 else fp32
                   int N, int K, int out_fp16)
{
    constexpr int TILE_BBt = BN * ROWB;
    constexpr int STAGE    = TILE_A + TILE_BBt;
    constexpr int NFRAG    = BN / 64;
    constexpr int WNW      = BN / 4;

    extern __shared__ __align__(16) unsigned char dsm[];
    const uint32_t sb = smem_u32(dsm);

    const int tid  = threadIdx.x;
    const int wid  = tid >> 5, lane = tid & 31;
    const int wm   = wid & 3;
    const int wn   = wid >> 2;
    const int m0   = blockIdx.y * G_BM;
    const int n0   = blockIdx.x * BN;

    const uint32_t frag_off = (uint32_t)((lane & 15) * ROWB + (lane >> 4) * 16);

    float acc[2][NFRAG * 2][4];
    #pragma unroll
    for (int i = 0; i < 2; i++)
        #pragma unroll
        for (int j = 0; j < NFRAG * 2; j++)
            #pragma unroll
            for (int q = 0; q < 4; q++) acc[i][j][q] = 0.f;

    auto issue = [&](int it, int stg) {
        const int k0 = it * G_BK;
        const uint32_t st = sb + stg * STAGE;
        #pragma unroll
        for (int j = 0; j < 2; j++) {            // A: 1024 16B chunks
            int idx = tid + j * 512;
            int row = idx >> 3, c16 = idx & 7;
            CP_ASYNC16(st + (uint32_t)(row * ROWB + c16 * 16),
                       Ah + (size_t)(m0 + row) * K + k0 + c16 * 8);
        }
        #pragma unroll
        for (int j = 0; j < BN / 64; j++) {      // B: BN*8 16B chunks
            int idx = tid + j * 512;
            int row = idx >> 3, c16 = idx & 7;
            CP_ASYNC16(st + TILE_A + (uint32_t)(row * ROWB + c16 * 16),
                       Wh + (size_t)(n0 + row) * K + k0 + c16 * 8);
        }
    };

    const int KC = K / G_BK;
    issue(0, 0); CP_COMMIT();
    issue(1, 1); CP_COMMIT();

    int s_rd = 0, s_wr = 2;
    for (int it = 0; it < KC; it++) {
        if (it + 1 < KC) CP_WAIT1(); else CP_WAIT0();
        __syncthreads();

        if (it + 2 < KC) { issue(it + 2, s_wr); CP_COMMIT(); }

        const uint32_t st = sb + s_rd * STAGE;
        #pragma unroll
        for (int kc = 0; kc < 4; kc++) {
            uint32_t a[2][4], b[NFRAG][4];
            #pragma unroll
            for (int mi = 0; mi < 2; mi++) {
                uint32_t base = (uint32_t)((wm * 32 + mi * 16) * ROWB + kc * 32) + frag_off;
                ldsm_x4(a[mi], st + base);
            }
            #pragma unroll
            for (int nj = 0; nj < NFRAG; nj++) {
                uint32_t base = (uint32_t)((wn * WNW + nj * 16) * ROWB + kc * 32) + frag_off;
                ldsm_x4(b[nj], st + TILE_A + base);
            }
            #pragma unroll
            for (int mi = 0; mi < 2; mi++)
                #pragma unroll
                for (int nj = 0; nj < NFRAG; nj++)
                    #pragma unroll
                    for (int h = 0; h < 2; h++)
                        mma_fp16(acc[mi][nj * 2 + h], a[mi], b[nj][h], b[nj][h + 2]);
        }
        s_rd = (s_rd + 1 == 3) ? 0 : s_rd + 1;
        s_wr = (s_wr + 1 == 3) ? 0 : s_wr + 1;
    }

    // ---- epilogue ----
    const int lg = lane >> 2;
    const int lq = lane & 3;
    if (out_fp16) {
        __half* C = (__half*)Cout;
        #pragma unroll
        for (int mi = 0; mi < 2; mi++) {
            const int mbase = m0 + wm * 32 + mi * 16 + lg;
            #pragma unroll
            for (int ni = 0; ni < NFRAG * 2; ni++) {
                const int n = n0 + wn * WNW + ni * 8 + lq * 2;
                float2 bv = *(const float2*)(bias + n);
                float* a = acc[mi][ni];
                *(uint32_t*)(C + (size_t)mbase * N + n) =
                    pack_h2(a[0] + bv.x, a[1] + bv.y);
                *(uint32_t*)(C + (size_t)(mbase + 8) * N + n) =
                    pack_h2(a[2] + bv.x, a[3] + bv.y);
            }
        }
    } else {
        float* C = (float*)Cout;
        #pragma unroll
        for (int mi = 0; mi < 2; mi++) {
            const int mbase = m0 + wm * 32 + mi * 16 + lg;
            #pragma unroll
            for (int ni = 0; ni < NFRAG * 2; ni++) {
                const int n = n0 + wn * WNW + ni * 8 + lq * 2;
                float2 bv = *(const float2*)(bias + n);
                float* a = acc[mi][ni];
                float2 o0 = make_float2(a[0] + bv.x, a[1] + bv.y);
                float2 o1 = make_float2(a[2] + bv.x, a[3] + bv.y);
                if (resid) {
                    float2 r0 = *(const float2*)(resid + (size_t)mbase * N + n);
                    float2 r1 = *(const float2*)(resid + (size_t)(mbase + 8) * N + n);
                    o0.x += r0.x; o0.y += r0.y;
                    o1.x += r1.x; o1.y += r1.y;
                }
                *(float2*)(C + (size_t)mbase * N + n)       = o0;
                *(float2*)(C + (size_t)(mbase + 8) * N + n) = o1;
            }
        }
    }
}

static constexpr int SMEM_BN256 = 3 * (TILE_A + 256 * ROWB);  // 165888
static constexpr int SMEM_BN128 = 3 * (TILE_A + 128 * ROWB);  // 110592

// ===========================================================================
// Merged prologue: one launch covers LN + wconv(w1) + wconv(w2) + wbar.
// Block ranges (256 threads each):
//   [0, 2048)            LayerNorm, 8 rows/block (warp-per-row)
//   [2048, 6144)         w1 fp32->fp16 (1,048,576 float4 chunks)
//   [6144, 8192)         w2 fp32->fp16 (524,288 float4 chunks)
//   [8192, 8200)         wbar (2048 channels)
// ===========================================================================
static constexpr int PB_LN  = 2048;
static constexpr int PB_W1  = 4096;   // (2*DI*DM)/4 / 256
static constexpr int PB_W2  = 2048;   // (DM*DI)/4 / 256
static constexpr int PB_ALL = PB_LN + PB_W1 + PB_W2 + 8;

__global__ __launch_bounds__(256)
void prologue_k(const float* __restrict__ x,
                const float* __restrict__ w,
                const float* __restrict__ b,
                const float* __restrict__ in_w,
                const float* __restrict__ out_w,
                const float* __restrict__ xproj_w)
{
    const int bid = blockIdx.x;
    const int tid = threadIdx.x;

    if (bid < PB_LN) {
        // ---- LayerNorm -> fp16 plane (warp-per-row, shuffle-only) ----
        const int lane = tid & 31, wrp = tid >> 5;
        const size_t row = (size_t)bid * 8 + wrp;

        const float4* xr = (const float4*)(x + row * DM);
        float4 v[8];
        float s = 0.f, ss = 0.f;
        #pragma unroll
        for (int j = 0; j < 8; j++) {
            v[j] = xr[lane + j * 32];
            s  += v[j].x + v[j].y + v[j].z + v[j].w;
            ss += v[j].x * v[j].x + v[j].y * v[j].y + v[j].z * v[j].z + v[j].w * v[j].w;
        }
        #pragma unroll
        for (int off = 16; off >= 1; off >>= 1) {
            s  += __shfl_xor_sync(0xffffffffu, s,  off);
            ss += __shfl_xor_sync(0xffffffffu, ss, off);
        }
        const float mu   = s * (1.f / DM);
        const float var  = ss * (1.f / DM) - mu * mu;
        const float rstd = rsqrtf(var + 1e-5f);

        #pragma unroll
        for (int j = 0; j < 8; j++) {
            const int c = (lane + j * 32) * 4;
            const float4 wv = *(const float4*)(w + c);
            const float4 bv = *(const float4*)(b + c);
            float o0 = (v[j].x - mu) * rstd * wv.x + bv.x;
            float o1 = (v[j].y - mu) * rstd * wv.y + bv.y;
            float o2 = (v[j].z - mu) * rstd * wv.z + bv.z;
            float o3 = (v[j].w - mu) * rstd * wv.w + bv.w;
            *(uint2*)(g_xn + row * DM + c) =
                make_uint2(pack_h2(o0, o1), pack_h2(o2, o3));
        }
    } else if (bid < PB_LN + PB_W1) {
        // ---- w1 convert ----
        size_t i = (size_t)(bid - PB_LN) * 256 + tid;
        float4 v = *(const float4*)(in_w + i * 4);
        *(uint2*)(g_w1 + i * 4) =
            make_uint2(pack_h2(v.x, v.y), pack_h2(v.z, v.w));
    } else if (bid < PB_LN + PB_W1 + PB_W2) {
        // ---- w2 convert ----
        size_t i = (size_t)(bid - PB_LN - PB_W1) * 256 + tid;
        float4 v = *(const float4*)(out_w + i * 4);
        *(uint2*)(g_w2 + i * 4) =
            make_uint2(pack_h2(v.x, v.y), pack_h2(v.z, v.w));
    } else {
        // ---- wbar ----
        int c = (bid - PB_LN - PB_W1 - PB_W2) * 256 + tid;
        if (c < DI) {
            float s = 0.f;
            #pragma unroll
            for (int k = 0; k < 16; k++)
                s += xproj_w[(size_t)(17 + k) * DI + c];
            g_wbar[c] = s * (1.f / 16.f);
        }
    }
}

// ---------------------------------------------------------------------------
// Fused mid: conv(4) + SiLU + gate + z-gate -> fp16 plane of y.
// Single-timestep form; z-load HOISTED above the barrier so its DRAM
// latency overlaps the barrier wait (gate-independent load).
// ---------------------------------------------------------------------------
#define TT 16

__global__ __launch_bounds__(256)
void fused_mid_k(const float* __restrict__ conv_w,
                 const float* __restrict__ conv_b,
                 const float* __restrict__ Dp)
{
    __shared__ float red[2][8];
    const int b   = blockIdx.y;
    const int t0  = blockIdx.x * TT;
    const int tid = threadIdx.x;
    const int lane = tid & 31, wrp = tid >> 5;
    const int c0 = tid * 8;

    float cw0[8], cw1[8], cw2[8], cw3[8], cb[8], wb[8], dd[8];
    #pragma unroll
    for (int i = 0; i < 8; i++) {
        float4 q = *(const float4*)(conv_w + (size_t)(c0 + i) * 4);
        cw0[i] = q.x; cw1[i] = q.y; cw2[i] = q.z; cw3[i] = q.w;
        cb[i] = conv_b[c0 + i];
        wb[i] = g_wbar[c0 + i];
        dd[i] = Dp[c0 + i];
    }

    float w0[8], w1[8], w2[8];
    #pragma unroll
    for (int j = 0; j < 3; j++) {
        int t = t0 - 3 + j;
        float* dst = (j == 0) ? w0 : (j == 1) ? w1 : w2;
        if (t >= 0) {
            load8h(dst, g_xz + ((size_t)b * TD + t) * (2 * DI) + c0);
        } else {
            #pragma unroll
            for (int i = 0; i < 8; i++) dst[i] = 0.f;
        }
    }

    for (int tt = 0; tt < TT; tt++) {
        const int t = t0 + tt;
        const int par = tt & 1;
        const size_t rb = ((size_t)b * TD + t) * (2 * DI);

        float cur[8];
        load8h(cur, g_xz + rb + c0);

        float xc[8], partial = 0.f;
        #pragma unroll
        for (int i = 0; i < 8; i++) {
            float a = cb[i] + w0[i]*cw0[i] + w1[i]*cw1[i] + w2[i]*cw2[i] + cur[i]*cw3[i];
            float sg = 1.f / (1.f + __expf(-a));
            xc[i] = a * sg;
            partial += xc[i] * wb[i];
        }

        #pragma unroll
        for (int off = 16; off >= 1; off >>= 1)
            partial += __shfl_xor_sync(0xffffffffu, partial, off);
        if (lane == 0) red[par][wrp] = partial;

        // z-load issued BEFORE the barrier: DRAM latency overlaps barrier wait
        float zv[8];
        load8h(zv, g_xz + rb + DI + c0);

        __syncthreads();
        float ssum = 0.f;
        #pragma unroll
        for (int k = 0; k < 8; k++) ssum += red[par][k];
        const float gate = 1.f / (1.f + __expf(-ssum));

        float out[8];
        #pragma unroll
        for (int i = 0; i < 8; i++) {
            float sz = zv[i] / (1.f + __expf(-zv[i]));
            out[i] = xc[i] * (gate + dd[i]) * sz;
        }

        size_t yo = ((size_t)b * TD + t) * DI + c0;
        *(uint4*)(g_y + yo) = make_uint4(
            pack_h2(out[0], out[1]), pack_h2(out[2], out[3]),
            pack_h2(out[4], out[5]), pack_h2(out[6], out[7]));

        #pragma unroll
        for (int i = 0; i < 8; i++) { w0[i] = w1[i]; w1[i] = w2[i]; w2[i] = cur[i]; }
    }
}

// ---------------------------------------------------------------------------
extern "C" void kernel_launch(void* const* d_in, const int* in_sizes, int n_in,
                              void* d_out, int out_size)
{
    const float* x       = (const float*)d_in[0];
    const float* norm_w  = (const float*)d_in[1];
    const float* norm_b  = (const float*)d_in[2];
    const float* in_w    = (const float*)d_in[3];
    const float* in_b    = (const float*)d_in[4];
    const float* conv_w  = (const float*)d_in[5];
    const float* conv_b  = (const float*)d_in[6];
    const float* xproj_w = (const float*)d_in[7];
    const float* Dp      = (const float*)d_in[9];
    const float* out_w   = (const float*)d_in[10];
    const float* out_b   = (const float*)d_in[11];
    float* out = (float*)d_out;

    __half *xn_p, *xz_p, *y_p, *w1_p, *w2_p;
    cudaGetSymbolAddress((void**)&xn_p, g_xn);
    cudaGetSymbolAddress((void**)&xz_p, g_xz);
    cudaGetSymbolAddress((void**)&y_p,  g_y);
    cudaGetSymbolAddress((void**)&w1_p, g_w1);
    cudaGetSymbolAddress((void**)&w2_p, g_w2);

    static int smem_set = 0;
    if (!smem_set) {
        cudaFuncSetAttribute(gemm_hmma_f16<256>,
                             cudaFuncAttributeMaxDynamicSharedMemorySize, SMEM_BN256);
        cudaFuncSetAttribute(gemm_hmma_f16<128>,
                             cudaFuncAttributeMaxDynamicSharedMemorySize, SMEM_BN128);
        smem_set = 1;
    }

    // Merged prologue: LN + both weight converts + wbar in ONE launch
    prologue_k<<<PB_ALL, 256>>>(x, norm_w, norm_b, in_w, out_w, xproj_w);

    // GEMM1: xz = xn @ in_w.T + in_b   (M=16384, N=4096, K=1024) -> fp16
    gemm_hmma_f16<256><<<dim3((2 * DI) / 256, (int)MROWS / G_BM), 512, SMEM_BN256>>>(
        xn_p, w1_p, in_b, nullptr, xz_p, 2 * DI, DM, 1);

    // conv + silu + gate + z-gate -> y (fp16)
    fused_mid_k<<<dim3(TD / TT, BD), 256>>>(conv_w, conv_b, Dp);

    // GEMM2: out = y @ out_w.T + out_b + x  (M=16384, N=1024, K=2048) -> fp32
    gemm_hmma_f16<128><<<dim3(DM / 128, (int)MROWS / G_BM), 512, SMEM_BN128>>>(
        y_p, w2_p, out_b, x, out, DM, DI, 0);
}